// round 13
// baseline (speedup 1.0000x reference)
#include <cuda_runtime.h>
#include <cstddef>

#define BB 64
#define SS 1024
#define HH 128
#define AA 8
#define WW 5
#define PADW 2
#define CH2 256         // s-rows per K1 block (k=2 s-block, h-split-2)
#define RSTRIDE 132     // padded smem row stride (floats); conflict-free LDS.128

// Scratch (allocation-free rule: __device__ globals)
__device__ float g_C[AA * WW * HH];        // C[a][w][h]
__device__ float g_logits[BB * AA * SS];   // [b][a][s]

// packed 2xFP32 FMA (FFMA2; PTX-only)
__device__ __forceinline__ void ffma2(unsigned long long& d,
                                      unsigned long long a,
                                      unsigned long long b) {
    asm("fma.rn.f32x2 %0, %1, %2, %0;" : "+l"(d) : "l"(a), "l"(b));
}
__device__ __forceinline__ float f32x2_hsum(unsigned long long v) {
    float lo = __uint_as_float((unsigned)(v & 0xffffffffull));
    float hi = __uint_as_float((unsigned)(v >> 32));
    return lo + hi;
}
__device__ __forceinline__ unsigned long long dup_f32(float a) {
    unsigned long long r;
    asm("mov.b64 %0, {%1, %1};" : "=l"(r) : "f"(a));
    return r;
}

// ---------------- Kernel C: combined conv weights (R11, unchanged) ----------------
__global__ void kc_kernel(const float* __restrict__ aspProj,
                          const float* __restrict__ Wt) {
    __shared__ float Wsm[HH * WW];
    int a    = blockIdx.x / 10;
    int part = blockIdx.x % 10;

    int rl = threadIdx.x >> 3;
    int fo = threadIdx.x & 7;
    int r  = part * 64 + rl;
    int h  = r / WW, w = r % WW;

    const float4* ap = (const float4*)(aspProj + ((size_t)a * HH + h) * HH + fo * 16);
    float4 x0 = ap[0], x1 = ap[1], x2 = ap[2], x3 = ap[3];

    for (int i = threadIdx.x; i < HH * WW; i += blockDim.x)
        Wsm[i] = Wt[a * HH * WW + i];
    __syncthreads();

    int f0 = fo * 16;
    float acc =
          x0.x * Wsm[(f0 + 0) * WW + w] + x0.y * Wsm[(f0 + 1) * WW + w]
        + x0.z * Wsm[(f0 + 2) * WW + w] + x0.w * Wsm[(f0 + 3) * WW + w]
        + x1.x * Wsm[(f0 + 4) * WW + w] + x1.y * Wsm[(f0 + 5) * WW + w]
        + x1.z * Wsm[(f0 + 6) * WW + w] + x1.w * Wsm[(f0 + 7) * WW + w]
        + x2.x * Wsm[(f0 + 8) * WW + w] + x2.y * Wsm[(f0 + 9) * WW + w]
        + x2.z * Wsm[(f0 +10) * WW + w] + x2.w * Wsm[(f0 +11) * WW + w]
        + x3.x * Wsm[(f0 +12) * WW + w] + x3.y * Wsm[(f0 +13) * WW + w]
        + x3.z * Wsm[(f0 +14) * WW + w] + x3.w * Wsm[(f0 +15) * WW + w];

    acc += __shfl_xor_sync(~0u, acc, 1);
    acc += __shfl_xor_sync(~0u, acc, 2);
    acc += __shfl_xor_sync(~0u, acc, 4);
    if (fo == 0)
        g_C[(a * WW + w) * HH + h] = acc;
}

// ---------------- Kernel 1: windowed logits (R9-proven, unchanged) ----------------
__global__ void k1_kernel(const float* __restrict__ doc) {
    extern __shared__ float sm[];
    float* rows = sm;                              // (CH2+4) * RSTRIDE = 34320
    float* Cbs  = rows + (CH2 + 4) * RSTRIDE;      // 5120
    float* redb = Cbs + AA * WW * HH;              // AA*CH2 = 2048

    int b   = blockIdx.y;
    int s0  = blockIdx.x * CH2;
    int tid = threadIdx.x;                         // 0..255
    int hg  = tid >> 7;                            // h-half
    int ts  = tid & 127;                           // s slot

    for (int i = tid; i < AA * WW * HH; i += 256)
        Cbs[i] = g_C[i];

    const int total = (CH2 + 4) * HH;              // 33280
    for (int idx = tid * 4; idx < total; idx += 256 * 4) {
        int r = idx >> 7;
        int c = idx & (HH - 1);
        int gs = s0 - PADW + r;
        float4 v = make_float4(0.f, 0.f, 0.f, 0.f);
        if (gs >= 0 && gs < SS)
            v = *(const float4*)&doc[((size_t)(b * SS + gs)) * HH + c];
        *(float4*)&rows[r * RSTRIDE + c] = v;
    }
    __syncthreads();

    unsigned long long accA[AA], accB[AA];
#pragma unroll
    for (int a = 0; a < AA; ++a) { accA[a] = 0ull; accB[a] = 0ull; }

    const int hoff = hg * 64;
#pragma unroll
    for (int w = 0; w < WW; ++w) {
        const ulonglong2* rpA = (const ulonglong2*)(rows + (ts + w) * RSTRIDE + hoff);
        const ulonglong2* rpB = (const ulonglong2*)(rows + (ts + 128 + w) * RSTRIDE + hoff);
#pragma unroll 4
        for (int h4 = 0; h4 < 16; ++h4) {          // 16 x float4 = 64 h
            ulonglong2 xA = rpA[h4];
            ulonglong2 xB = rpB[h4];
#pragma unroll
            for (int a = 0; a < AA; ++a) {
                ulonglong2 c = *(const ulonglong2*)&Cbs[(a * WW + w) * HH + hoff + 4 * h4];
                ffma2(accA[a], xA.x, c.x);
                ffma2(accA[a], xA.y, c.y);
                ffma2(accB[a], xB.x, c.x);
                ffma2(accB[a], xB.y, c.y);
            }
        }
    }

    if (hg == 1) {
#pragma unroll
        for (int a = 0; a < AA; ++a) {
            redb[a * CH2 + ts]       = f32x2_hsum(accA[a]);
            redb[a * CH2 + 128 + ts] = f32x2_hsum(accB[a]);
        }
    }
    __syncthreads();
    if (hg == 0) {
#pragma unroll
        for (int a = 0; a < AA; ++a) {
            float* lg = g_logits + ((size_t)b * AA + a) * SS + s0;
            lg[ts]       = f32x2_hsum(accA[a]) + redb[a * CH2 + ts];
            lg[128 + ts] = f32x2_hsum(accB[a]) + redb[a * CH2 + 128 + ts];
        }
    }
}

// ---------------- Kernel 2: 512 threads, no spills, single-round reduction ----------------
#define AH 4   // aspects per block
// dyn smem layout (floats):
//   attn : AH*SS          = 4096   (16KB)
//   P    : 16*AH*HH       = 8192   (32KB)  warp-partials, warp-disjoint
//   Tb   : AH*HH          = 512    (2KB)
//   red  : 16 + 4
__global__ void __launch_bounds__(512, 2)
k2_kernel(const float* __restrict__ doc,
          const float* __restrict__ aspProj,
          float* __restrict__ out) {
    extern __shared__ __align__(16) float sm2[];
    float* attn = sm2;                     // 4096
    float* P    = attn + AH * SS;          // 8192
    float* Tb   = P + 16 * AH * HH;        // 512
    float* red  = Tb + AH * HH;            // 16
    float* redA = red + 16;                // 4

    int b    = blockIdx.x;
    int a_lo = blockIdx.y * AH;
    int tid  = threadIdx.x;                // 0..511
    int lane = tid & 31;
    int warp = tid >> 5;                   // 0..15

    // ---- Phase A: 4 concurrent softmaxes (128 threads per aspect; no-max,
    //      logits are tiny so exp is overflow-safe) ----
    {
        int ga = tid >> 7;       // local aspect 0..3
        int gs = tid & 127;
        float e[8];
        const float* lg = g_logits + ((size_t)b * AA + a_lo + ga) * SS + gs;

        float s = 0.f;
#pragma unroll
        for (int k = 0; k < 8; ++k) { e[k] = __expf(lg[128 * k]); s += e[k]; }
#pragma unroll
        for (int o = 16; o; o >>= 1) s += __shfl_xor_sync(~0u, s, o);
        if (lane == 0) red[warp] = s;
        __syncthreads();
        if (warp == 0 && lane < 16) {
            float x = red[lane];
            x += __shfl_xor_sync(0xffffu, x, 1);
            x += __shfl_xor_sync(0xffffu, x, 2);
            if ((lane & 3) == 0) redA[lane >> 2] = x;
        }
        __syncthreads();
        float inv = 1.f / redA[ga];

        float* osm = attn + ga * SS + gs;
        float* og  = out + ((size_t)b * AA + a_lo + ga) * SS + gs;
#pragma unroll
        for (int k = 0; k < 8; ++k) {
            float at = e[k] * inv;
            osm[128 * k] = at;
            og[128 * k]  = at;
        }
    }
    __syncthreads();

    // ---- Phase B: T[a][h] = sum_s doc[b,s,h] * attn[a][s] ----
    // warp w handles s = w + 16*it (64 iters); lane = h-float4 column.
    unsigned long long tp2[AH * 2];
#pragma unroll
    for (int i = 0; i < AH * 2; ++i) tp2[i] = 0ull;

    const float* dbase = doc + (size_t)b * SS * HH + 4 * lane;
#pragma unroll 8
    for (int it = 0; it < 64; ++it) {
        int s = warp + it * 16;
        ulonglong2 x = *(const ulonglong2*)&dbase[(size_t)s * HH];
#pragma unroll
        for (int a = 0; a < AH; ++a) {
            unsigned long long aw2 = dup_f32(attn[a * SS + s]);
            ffma2(tp2[2 * a + 0], x.x, aw2);
            ffma2(tp2[2 * a + 1], x.y, aw2);
        }
    }

    // single-round reduction: warp-disjoint slots, one barrier, one gather
#pragma unroll
    for (int a = 0; a < AH; ++a)
        *(float4*)&P[((warp * AH + a) * HH) + 4 * lane] =
            *reinterpret_cast<float4*>(&tp2[2 * a]);
    __syncthreads();

    {   // tid < 512 covers all AH*HH = 512 entries
        int a = tid >> 7;
        int h = tid & 127;
        float r = 0.f;
#pragma unroll
        for (int w2 = 0; w2 < 16; ++w2)
            r += P[((w2 * AH + a) * HH) + h];
        Tb[a * HH + h] = r;
    }
    __syncthreads();

    // ---- Phase C: rep[a][ho] = sum_h T[a][h] * aspProj[a_g][h][ho] ----
    {
        int a  = tid >> 7;           // local aspect 0..3
        int ho = tid & 127;          // output column (lane-contiguous -> coalesced)
        const float* apB = aspProj + (size_t)(a_lo + a) * HH * HH + ho;
        float acc = 0.f;
#pragma unroll 8
        for (int h = 0; h < HH; ++h)
            acc += Tb[a * HH + h] * apB[(size_t)h * HH];
        size_t off = (size_t)BB * AA * SS + ((size_t)b * AA + a_lo + a) * HH + ho;
        out[off] = acc;
    }
}

extern "C" void kernel_launch(void* const* d_in, const int* in_sizes, int n_in,
                              void* d_out, int out_size) {
    const float* doc     = (const float*)d_in[0];  // (64,1024,128) f32
    const float* Wt      = (const float*)d_in[1];  // (8, 640) f32
    const float* aspProj = (const float*)d_in[2];  // (8,128,128) f32
    float* out = (float*)d_out;

    kc_kernel<<<80, 512>>>(aspProj, Wt);

    size_t sm1 = ((size_t)(CH2 + 4) * RSTRIDE + (size_t)AA * WW * HH
                + (size_t)AA * CH2) * sizeof(float);   // ~166 KB
    cudaFuncSetAttribute(k1_kernel, cudaFuncAttributeMaxDynamicSharedMemorySize, (int)sm1);
    k1_kernel<<<dim3(SS / CH2, BB), 256, sm1>>>(doc);

    size_t sm2 = (size_t)(AH * SS + 16 * AH * HH + AH * HH + 16 + 4) * sizeof(float); // ~50.3 KB
    cudaFuncSetAttribute(k2_kernel, cudaFuncAttributeMaxDynamicSharedMemorySize, (int)sm2);
    k2_kernel<<<dim3(BB, 2), 512, sm2>>>(doc, aspProj, out);
}

// round 14
// speedup vs baseline: 1.1353x; 1.1353x over previous
#include <cuda_runtime.h>
#include <cstddef>

#define BB 64
#define SS 1024
#define HH 128
#define AA 8
#define WW 5
#define PADW 2
#define CH2 256         // s-rows per phase-1 unit
#define RSTRIDE 132     // padded smem row stride (floats); conflict-free LDS.128
#define NBLK 128        // grid size (all co-resident: 1 CTA/SM, 128 <= 148 SMs)

// Scratch (allocation-free rule: __device__ globals)
__device__ float g_C[AA * WW * HH];        // C[a][w][h]
__device__ float g_logits[BB * AA * SS];   // [b][a][s]
__device__ unsigned g_bar_arrive = 0;      // grid barrier state (self-resetting)
__device__ unsigned g_bar_gen    = 0;

// packed 2xFP32 FMA (FFMA2; PTX-only)
__device__ __forceinline__ void ffma2(unsigned long long& d,
                                      unsigned long long a,
                                      unsigned long long b) {
    asm("fma.rn.f32x2 %0, %1, %2, %0;" : "+l"(d) : "l"(a), "l"(b));
}
__device__ __forceinline__ float f32x2_hsum(unsigned long long v) {
    float lo = __uint_as_float((unsigned)(v & 0xffffffffull));
    float hi = __uint_as_float((unsigned)(v >> 32));
    return lo + hi;
}
__device__ __forceinline__ unsigned long long dup_f32(float a) {
    unsigned long long r;
    asm("mov.b64 %0, {%1, %1};" : "=l"(r) : "f"(a));
    return r;
}

// Grid-wide barrier: all NBLK blocks are co-resident (1 CTA/SM), so spinning
// is deadlock-free. Arrive counter resets every use -> clean across graph
// replays. Generation counter only ever increments (wraps harmlessly).
__device__ __forceinline__ void grid_bar() {
    __syncthreads();
    if (threadIdx.x == 0) {
        unsigned gen = *((volatile unsigned*)&g_bar_gen);
        __threadfence();
        if (atomicAdd(&g_bar_arrive, 1u) == (unsigned)(NBLK - 1)) {
            g_bar_arrive = 0u;
            __threadfence();
            atomicExch(&g_bar_gen, gen + 1u);
        } else {
            while (*((volatile unsigned*)&g_bar_gen) == gen) { }
        }
        __threadfence();
    }
    __syncthreads();
}

// ================= fused kernel: C-fold + logits + softmax/T/rep =================
// dyn smem (floats), phase 1 layout:
//   rows : (CH2+4)*RSTRIDE = 34320
//   Cbs  : AA*WW*HH        = 5120
//   redb : 4*AA*CH2        = 8192     (h-quarter partials)
// phase 2 aliases the same region:
//   attn : 4*SS = 4096 | P : 16*4*HH = 8192 | Tb : 512 | red : 16 | redA : 4
__global__ void __launch_bounds__(512, 1)
fused_kernel(const float* __restrict__ doc,
             const float* __restrict__ Wt,
             const float* __restrict__ aspProj,
             float* __restrict__ out) {
    extern __shared__ __align__(16) float sm[];
    int blk = blockIdx.x;
    int tid = threadIdx.x;                 // 0..511
    int lane = tid & 31;
    int warp = tid >> 5;

    // ---------------- Phase 0: C[a,w,h] (verbatim kc on blocks 0..79) ----------------
    if (blk < 80) {
        float* Wsm = sm;                   // HH*WW = 640 floats
        int a    = blk / 10;
        int part = blk % 10;

        int rl = tid >> 3;
        int fo = tid & 7;
        int r  = part * 64 + rl;
        int h  = r / WW, w = r % WW;

        const float4* ap = (const float4*)(aspProj + ((size_t)a * HH + h) * HH + fo * 16);
        float4 x0 = ap[0], x1 = ap[1], x2 = ap[2], x3 = ap[3];

        for (int i = tid; i < HH * WW; i += 512)
            Wsm[i] = Wt[a * HH * WW + i];
        __syncthreads();

        int f0 = fo * 16;
        float acc =
              x0.x * Wsm[(f0 + 0) * WW + w] + x0.y * Wsm[(f0 + 1) * WW + w]
            + x0.z * Wsm[(f0 + 2) * WW + w] + x0.w * Wsm[(f0 + 3) * WW + w]
            + x1.x * Wsm[(f0 + 4) * WW + w] + x1.y * Wsm[(f0 + 5) * WW + w]
            + x1.z * Wsm[(f0 + 6) * WW + w] + x1.w * Wsm[(f0 + 7) * WW + w]
            + x2.x * Wsm[(f0 + 8) * WW + w] + x2.y * Wsm[(f0 + 9) * WW + w]
            + x2.z * Wsm[(f0 +10) * WW + w] + x2.w * Wsm[(f0 +11) * WW + w]
            + x3.x * Wsm[(f0 +12) * WW + w] + x3.y * Wsm[(f0 +13) * WW + w]
            + x3.z * Wsm[(f0 +14) * WW + w] + x3.w * Wsm[(f0 +15) * WW + w];

        acc += __shfl_xor_sync(~0u, acc, 1);
        acc += __shfl_xor_sync(~0u, acc, 2);
        acc += __shfl_xor_sync(~0u, acc, 4);
        if (fo == 0)
            g_C[(a * WW + w) * HH + h] = acc;
    }
    grid_bar();

    // ---------------- Phase 1: windowed logits (2 units/block) ----------------
    {
        float* rows = sm;                              // 34320
        float* Cbs  = rows + (CH2 + 4) * RSTRIDE;      // 5120
        float* redb = Cbs + AA * WW * HH;              // 8192

        for (int i = tid; i < AA * WW * HH; i += 512)
            Cbs[i] = g_C[i];

        int hg   = tid >> 7;       // h-quarter 0..3 (32 h each)
        int ts   = tid & 127;      // s slot (pair: ts, ts+128)
        int hoff = hg * 32;

        for (int u = 0; u < 2; ++u) {
            int unit = blk * 2 + u;            // 0..255
            int b    = unit >> 2;
            int s0   = (unit & 3) * CH2;

            __syncthreads();   // protect rows/redb reuse across units
            const int total = (CH2 + 4) * HH;  // 33280
            for (int idx = tid * 4; idx < total; idx += 512 * 4) {
                int r = idx >> 7;
                int c = idx & (HH - 1);
                int gs = s0 - PADW + r;
                float4 v = make_float4(0.f, 0.f, 0.f, 0.f);
                if (gs >= 0 && gs < SS)
                    v = *(const float4*)&doc[((size_t)(b * SS + gs)) * HH + c];
                *(float4*)&rows[r * RSTRIDE + c] = v;
            }
            __syncthreads();

            unsigned long long accA[AA], accB[AA];
#pragma unroll
            for (int a = 0; a < AA; ++a) { accA[a] = 0ull; accB[a] = 0ull; }

#pragma unroll
            for (int w = 0; w < WW; ++w) {
                const ulonglong2* rpA = (const ulonglong2*)(rows + (ts + w) * RSTRIDE + hoff);
                const ulonglong2* rpB = (const ulonglong2*)(rows + (ts + 128 + w) * RSTRIDE + hoff);
#pragma unroll 4
                for (int h4 = 0; h4 < 8; ++h4) {       // 8 x float4 = 32 h
                    ulonglong2 xA = rpA[h4];
                    ulonglong2 xB = rpB[h4];
#pragma unroll
                    for (int a = 0; a < AA; ++a) {
                        ulonglong2 c = *(const ulonglong2*)&Cbs[(a * WW + w) * HH + hoff + 4 * h4];
                        ffma2(accA[a], xA.x, c.x);
                        ffma2(accA[a], xA.y, c.y);
                        ffma2(accB[a], xB.x, c.x);
                        ffma2(accB[a], xB.y, c.y);
                    }
                }
            }

            // publish h-quarter partials: redb[(hg*AA + a)*CH2 + s_local]
#pragma unroll
            for (int a = 0; a < AA; ++a) {
                redb[(hg * AA + a) * CH2 + ts]       = f32x2_hsum(accA[a]);
                redb[(hg * AA + a) * CH2 + 128 + ts] = f32x2_hsum(accB[a]);
            }
            __syncthreads();

            // combine 4 quarters: 2048 outputs, 4 per thread
            for (int o = tid; o < AA * CH2; o += 512) {
                int a = o >> 8;
                int s = o & (CH2 - 1);
                float v = redb[(0 * AA + a) * CH2 + s]
                        + redb[(1 * AA + a) * CH2 + s]
                        + redb[(2 * AA + a) * CH2 + s]
                        + redb[(3 * AA + a) * CH2 + s];
                g_logits[((size_t)b * AA + a) * SS + s0 + s] = v;
            }
        }
    }
    grid_bar();

    // ---------------- Phase 2: softmax + T + rep (R12 body; blk=(y,b)) ----------------
    {
        float* attn = sm;                      // 4096
        float* P    = attn + 4 * SS;           // 8192
        float* Tb   = P + 16 * 4 * HH;         // 512
        float* red  = Tb + 4 * HH;             // 16
        float* redA = red + 16;                // 4

        int b    = blk & 63;
        int a_lo = (blk >> 6) * 4;

        // Phase A: 4 concurrent softmaxes (128 threads/aspect; no-max — logits tiny)
        {
            int ga = tid >> 7;
            int gs = tid & 127;
            float e[8];
            const float* lg = g_logits + ((size_t)b * AA + a_lo + ga) * SS + gs;

            float s = 0.f;
#pragma unroll
            for (int k = 0; k < 8; ++k) { e[k] = __expf(lg[128 * k]); s += e[k]; }
#pragma unroll
            for (int o = 16; o; o >>= 1) s += __shfl_xor_sync(~0u, s, o);
            if (lane == 0) red[warp] = s;
            __syncthreads();
            if (warp == 0 && lane < 16) {
                float x = red[lane];
                x += __shfl_xor_sync(0xffffu, x, 1);
                x += __shfl_xor_sync(0xffffu, x, 2);
                if ((lane & 3) == 0) redA[lane >> 2] = x;
            }
            __syncthreads();
            float inv = 1.f / redA[ga];

            float* osm = attn + ga * SS + gs;
            float* og  = out + ((size_t)b * AA + a_lo + ga) * SS + gs;
#pragma unroll
            for (int k = 0; k < 8; ++k) {
                float at = e[k] * inv;
                osm[128 * k] = at;
                og[128 * k]  = at;
            }
        }
        __syncthreads();

        // Phase B: T[a][h] = sum_s doc[b,s,h] * attn[a][s]
        unsigned long long tp2[4 * 2];
#pragma unroll
        for (int i = 0; i < 8; ++i) tp2[i] = 0ull;

        const float* dbase = doc + (size_t)b * SS * HH + 4 * lane;
#pragma unroll 8
        for (int it = 0; it < 64; ++it) {
            int s = warp + it * 16;
            ulonglong2 x = *(const ulonglong2*)&dbase[(size_t)s * HH];
#pragma unroll
            for (int a = 0; a < 4; ++a) {
                unsigned long long aw2 = dup_f32(attn[a * SS + s]);
                ffma2(tp2[2 * a + 0], x.x, aw2);
                ffma2(tp2[2 * a + 1], x.y, aw2);
            }
        }

        // single-round reduction: warp-disjoint slots
#pragma unroll
        for (int a = 0; a < 4; ++a)
            *(float4*)&P[((warp * 4 + a) * HH) + 4 * lane] =
                *reinterpret_cast<float4*>(&tp2[2 * a]);
        __syncthreads();

        {
            int a = tid >> 7;
            int h = tid & 127;
            float r = 0.f;
#pragma unroll
            for (int w2 = 0; w2 < 16; ++w2)
                r += P[((w2 * 4 + a) * HH) + h];
            Tb[a * HH + h] = r;
        }
        __syncthreads();

        // Phase C: rep[a][ho] = sum_h T[a][h] * aspProj[a][h][ho]
        {
            int a  = tid >> 7;
            int ho = tid & 127;
            const float* apB = aspProj + (size_t)(a_lo + a) * HH * HH + ho;
            float acc = 0.f;
#pragma unroll 8
            for (int h = 0; h < HH; ++h)
                acc += Tb[a * HH + h] * apB[(size_t)h * HH];
            size_t off = (size_t)BB * AA * SS + ((size_t)b * AA + a_lo + a) * HH + ho;
            out[off] = acc;
        }
    }
}

extern "C" void kernel_launch(void* const* d_in, const int* in_sizes, int n_in,
                              void* d_out, int out_size) {
    const float* doc     = (const float*)d_in[0];  // (64,1024,128) f32
    const float* Wt      = (const float*)d_in[1];  // (8, 640) f32
    const float* aspProj = (const float*)d_in[2];  // (8,128,128) f32
    float* out = (float*)d_out;

    size_t smB = ((size_t)(CH2 + 4) * RSTRIDE + (size_t)AA * WW * HH
                + (size_t)4 * AA * CH2) * sizeof(float);   // ~190.5 KB
    cudaFuncSetAttribute(fused_kernel, cudaFuncAttributeMaxDynamicSharedMemorySize, (int)smB);
    fused_kernel<<<NBLK, 512, smB>>>(doc, Wt, aspProj, out);
}